// round 14
// baseline (speedup 1.0000x reference)
#include <cuda_runtime.h>
#include <cuda_fp16.h>

// Problem constants: 50000 nodes, 256 feats, 400000 edges,
// DIFF_T=1.0, N_SEG=4 (t_seg=0.25), N_TERMS=8.
#define NN_MAX 50000
#define DF 256
#define DF4 (DF / 4)
#define NE_MAX 400000

// Scratch (allocation-free: static device globals).
__device__ int   g_cnt[NN_MAX + 1];
__device__ int   g_rowptr[NN_MAX + 1];
__device__ int   g_fill[NN_MAX];
__device__ int   g_sums[64];
__device__ int   g_offs[64];
__device__ int2  g_cv[NE_MAX];           // packed {col, val-bits}
__device__ float g_deg[NN_MAX];
// fp16 state buffers: y mirror + z ping-pong (global side).
__device__ __half g_hy[(size_t)NN_MAX * DF];
__device__ __half g_half0[(size_t)NN_MAX * DF];
__device__ __half g_half1[(size_t)NN_MAX * DF];

// Global software barrier state (replay-safe).
__device__ int g_bar_count;
__device__ int g_bar_sense;

// ---------------------------------------------------------------------------
// CSR build: 5 launches total before the persistent kernel so that
// ncu -s 5 -c 1 profiles persistent_horner itself.
//   [0] init  [1] count_deg  [2] scan1  [3] scan2  [4] scan3  [5] persistent
// ---------------------------------------------------------------------------
__global__ void init_kernel(int nn) {
    int i = blockIdx.x * blockDim.x + threadIdx.x;
    if (i <= nn) g_cnt[i] = 0;
    if (i < nn) g_deg[i] = 0.f;
}

__global__ void count_deg_kernel(const int* __restrict__ rows,
                                 const float* __restrict__ vals, int ne) {
    int e = blockIdx.x * blockDim.x + threadIdx.x;
    if (e < ne) {
        int r = rows[e];
        atomicAdd(&g_cnt[r], 1);
        atomicAdd(&g_deg[r], vals[e]);
    }
}

__global__ void scan1_kernel(int n) {
    __shared__ int sh[1024];
    int tid = threadIdx.x;
    int i = blockIdx.x * 1024 + tid;
    int v = (i < n) ? g_cnt[i] : 0;
    sh[tid] = v;
    __syncthreads();
    for (int off = 1; off < 1024; off <<= 1) {
        int t = (tid >= off) ? sh[tid - off] : 0;
        __syncthreads();
        sh[tid] += t;
        __syncthreads();
    }
    if (i < n) g_rowptr[i] = sh[tid] - v;
    if (tid == 1023) g_sums[blockIdx.x] = sh[1023];
}

__global__ void scan2_kernel(int nchunks) {
    if (blockIdx.x == 0 && threadIdx.x == 0) {
        int run = 0;
        for (int b = 0; b < nchunks; b++) {
            int s = g_sums[b];
            g_offs[b] = run;
            run += s;
        }
    }
}

__global__ void scan3_kernel(int n) {
    int i = blockIdx.x * 1024 + threadIdx.x;
    if (i < n) g_rowptr[i] += g_offs[blockIdx.x];
}

// ---------------------------------------------------------------------------
// One Horner row update (fp16 state):
//   znew[r] = y[r] + coef * ( deg[r]*z[r] - sum_e val_e * zh[col_e] )
//   gather + global read via hsrc; diag z[r] from smem slab (written by this
//   warp last step); y[r] from global hy (L1-resident within a segment).
//   Writes fp16 znew to hdst (global) AND smem slab; fp32 to dst32 if set.
// One warp per row; thread f owns feats [8f, 8f+8). 4-edge unroll (MLP=4).
// ---------------------------------------------------------------------------
__device__ __forceinline__ void horner_row(
    int r, int lr, int f,
    const uint4* __restrict__ hsrc,   // z mirror (gather), global
    uint4* __restrict__ s_z,          // smem z (block-local rows)
    const uint4* __restrict__ hy,     // y mirror (own-row read), global
    uint4* __restrict__ hdst,         // global fp16 dst
    float4* __restrict__ dst32,       // fp32 out (or nullptr)
    float coef)
{
    int start = g_rowptr[r];
    int end = g_rowptr[r + 1];

    float s0 = 0.f, s1 = 0.f, s2 = 0.f, s3 = 0.f;
    float s4 = 0.f, s5 = 0.f, s6 = 0.f, s7 = 0.f;

    for (int e = start; e < end; e += 4) {
        int last = end - 1;
        int e1 = min(e + 1, last);
        int e2 = min(e + 2, last);
        int e3 = min(e + 3, last);
        int2 cv0 = g_cv[e];
        int2 cv1 = g_cv[e1];
        int2 cv2 = g_cv[e2];
        int2 cv3 = g_cv[e3];
        float w0 = __int_as_float(cv0.y);
        float w1 = (e + 1 < end) ? __int_as_float(cv1.y) : 0.f;
        float w2 = (e + 2 < end) ? __int_as_float(cv2.y) : 0.f;
        float w3 = (e + 3 < end) ? __int_as_float(cv3.y) : 0.f;
        uint4 u0 = hsrc[(size_t)cv0.x * 32 + f];
        uint4 u1 = hsrc[(size_t)cv1.x * 32 + f];
        uint4 u2 = hsrc[(size_t)cv2.x * 32 + f];
        uint4 u3 = hsrc[(size_t)cv3.x * 32 + f];

        const __half2* h0 = (const __half2*)&u0;
        const __half2* h1 = (const __half2*)&u1;
        const __half2* h2 = (const __half2*)&u2;
        const __half2* h3 = (const __half2*)&u3;
        float2 p;
        p = __half22float2(h0[0]); s0 = fmaf(w0, p.x, s0); s1 = fmaf(w0, p.y, s1);
        p = __half22float2(h0[1]); s2 = fmaf(w0, p.x, s2); s3 = fmaf(w0, p.y, s3);
        p = __half22float2(h0[2]); s4 = fmaf(w0, p.x, s4); s5 = fmaf(w0, p.y, s5);
        p = __half22float2(h0[3]); s6 = fmaf(w0, p.x, s6); s7 = fmaf(w0, p.y, s7);
        p = __half22float2(h1[0]); s0 = fmaf(w1, p.x, s0); s1 = fmaf(w1, p.y, s1);
        p = __half22float2(h1[1]); s2 = fmaf(w1, p.x, s2); s3 = fmaf(w1, p.y, s3);
        p = __half22float2(h1[2]); s4 = fmaf(w1, p.x, s4); s5 = fmaf(w1, p.y, s5);
        p = __half22float2(h1[3]); s6 = fmaf(w1, p.x, s6); s7 = fmaf(w1, p.y, s7);
        p = __half22float2(h2[0]); s0 = fmaf(w2, p.x, s0); s1 = fmaf(w2, p.y, s1);
        p = __half22float2(h2[1]); s2 = fmaf(w2, p.x, s2); s3 = fmaf(w2, p.y, s3);
        p = __half22float2(h2[2]); s4 = fmaf(w2, p.x, s4); s5 = fmaf(w2, p.y, s5);
        p = __half22float2(h2[3]); s6 = fmaf(w2, p.x, s6); s7 = fmaf(w2, p.y, s7);
        p = __half22float2(h3[0]); s0 = fmaf(w3, p.x, s0); s1 = fmaf(w3, p.y, s1);
        p = __half22float2(h3[1]); s2 = fmaf(w3, p.x, s2); s3 = fmaf(w3, p.y, s3);
        p = __half22float2(h3[2]); s4 = fmaf(w3, p.x, s4); s5 = fmaf(w3, p.y, s5);
        p = __half22float2(h3[3]); s6 = fmaf(w3, p.x, s6); s7 = fmaf(w3, p.y, s7);
    }

    // Diagonal term from smem z (written by this warp last step).
    float d = g_deg[r];
    uint4 um = s_z[lr * 32 + f];
    const __half2* hm = (const __half2*)&um;
    float2 m01 = __half22float2(hm[0]);
    float2 m23 = __half22float2(hm[1]);
    float2 m45 = __half22float2(hm[2]);
    float2 m67 = __half22float2(hm[3]);

    // y term from global hy (L1-resident own-row read).
    uint4 uy = hy[(size_t)r * 32 + f];
    const __half2* hyv = (const __half2*)&uy;
    float2 y01 = __half22float2(hyv[0]);
    float2 y23 = __half22float2(hyv[1]);
    float2 y45 = __half22float2(hyv[2]);
    float2 y67 = __half22float2(hyv[3]);

    float o0 = fmaf(coef, fmaf(d, m01.x, -s0), y01.x);
    float o1 = fmaf(coef, fmaf(d, m01.y, -s1), y01.y);
    float o2 = fmaf(coef, fmaf(d, m23.x, -s2), y23.x);
    float o3 = fmaf(coef, fmaf(d, m23.y, -s3), y23.y);
    float o4 = fmaf(coef, fmaf(d, m45.x, -s4), y45.x);
    float o5 = fmaf(coef, fmaf(d, m45.y, -s5), y45.y);
    float o6 = fmaf(coef, fmaf(d, m67.x, -s6), y67.x);
    float o7 = fmaf(coef, fmaf(d, m67.y, -s7), y67.y);

    if (dst32) {
        size_t base = (size_t)r * DF4 + 2 * f;
        dst32[base]     = make_float4(o0, o1, o2, o3);
        dst32[base + 1] = make_float4(o4, o5, o6, o7);
    }

    __half2 h[4];
    h[0] = __floats2half2_rn(o0, o1);
    h[1] = __floats2half2_rn(o2, o3);
    h[2] = __floats2half2_rn(o4, o5);
    h[3] = __floats2half2_rn(o6, o7);
    uint4 packed = *(const uint4*)h;
    hdst[(size_t)r * 32 + f] = packed;
    s_z[lr * 32 + f] = packed;   // diag source for next step
}

// ---------------------------------------------------------------------------
// Persistent kernel. Prologue (replay-safe, behind global barriers):
//   phase 0: g_fill = g_rowptr
//   phase 1: scatter edges into g_cv; seed global hy = fp16(x); seed smem z.
// Main: 4 segments x 8 Horner steps, global barrier between steps.
// Grid sized host-side via occupancy API including smem (~8 blocks/SM).
// blockDim = (32, 8). Block owns R contiguous rows; z slab = R * 512B.
// ---------------------------------------------------------------------------
__device__ __forceinline__ void global_barrier(int* s_sense_p, int tid,
                                               int nblocks) {
    __syncthreads();
    if (tid == 0) {
        __threadfence();
        int want = *s_sense_p ^ 1;
        int old = atomicAdd(&g_bar_count, 1);
        if (old == nblocks - 1) {
            g_bar_count = 0;
            __threadfence();
            *(volatile int*)&g_bar_sense = want;
        } else {
            while (*(volatile int*)&g_bar_sense != want)
                __nanosleep(64);
        }
        __threadfence();
        *s_sense_p = want;
    }
    __syncthreads();
}

__global__ void __launch_bounds__(256)
persistent_horner(const float4* __restrict__ x,
                  const int* __restrict__ er,
                  const int* __restrict__ ec,
                  const float* __restrict__ ev,
                  float4* __restrict__ out,
                  uint4* __restrict__ hy,
                  uint4* __restrict__ h0,
                  uint4* __restrict__ h1,
                  int nn, int ne, int R, int nblocks) {
    extern __shared__ uint4 s_z[];   // R * 32 uint4
    __shared__ int s_sense;
    int tid = threadIdx.y * 32 + threadIdx.x;
    if (tid == 0) s_sense = *(volatile int*)&g_bar_sense;
    __syncthreads();

    int gtid = blockIdx.x * 256 + tid;
    int gstride = nblocks * 256;

    // --- Prologue phase 0: reset fill (replay-safe scatter base) ---
    for (int i = gtid; i < nn; i += gstride) g_fill[i] = g_rowptr[i];
    global_barrier(&s_sense, tid, nblocks);

    // --- Prologue phase 1: scatter + seed hy ---
    for (int e = gtid; e < ne; e += gstride) {
        int r = er[e];
        int pos = atomicAdd(&g_fill[r], 1);
        int2 cv;
        cv.x = ec[e];
        cv.y = __float_as_int(ev[e]);
        g_cv[pos] = cv;
    }
    int n4 = nn * 32;
    for (int i = gtid; i < n4; i += gstride) {
        float4 a = x[2 * i];
        float4 b = x[2 * i + 1];
        __half2 hh[4];
        hh[0] = __floats2half2_rn(a.x, a.y);
        hh[1] = __floats2half2_rn(a.z, a.w);
        hh[2] = __floats2half2_rn(b.x, b.y);
        hh[3] = __floats2half2_rn(b.z, b.w);
        hy[i] = *(const uint4*)hh;
    }

    int bstart = blockIdx.x * R;
    int bend = min(bstart + R, nn);
    int w = threadIdx.y;   // 0..7
    int f = threadIdx.x;   // 0..31

    // Seed smem z from x (z = y at segment-0 start).
    for (int r = bstart + w; r < bend; r += 8) {
        int lr = r - bstart;
        size_t base = (size_t)r * DF4 + 2 * f;
        float4 a = x[base];
        float4 b = x[base + 1];
        __half2 hh[4];
        hh[0] = __floats2half2_rn(a.x, a.y);
        hh[1] = __floats2half2_rn(a.z, a.w);
        hh[2] = __floats2half2_rn(b.x, b.y);
        hh[3] = __floats2half2_rn(b.z, b.w);
        s_z[lr * 32 + f] = *(const uint4*)hh;
    }
    global_barrier(&s_sense, tid, nblocks);

    // --- Main: 4 segments x 8 Horner steps ---
    int p = 0;  // which of h0/h1 is next write target for k=8..2
    for (int seg = 0; seg < 4; seg++) {
        const uint4* cur = hy;  // z mirror starts as y
        for (int k = 8; k >= 1; k--) {
            float coef = -0.25f / (float)k;
            bool final_step = (seg == 3) && (k == 1);
            uint4* hd;
            if (k == 1) {
                hd = hy;       // becomes next segment's y
            } else {
                hd = p ? h1 : h0;
                p ^= 1;
            }
            float4* dst32 = final_step ? out : nullptr;

            for (int r = bstart + w; r < bend; r += 8)
                horner_row(r, r - bstart, f, cur, s_z, hy, hd, dst32, coef);
            cur = hd;

            if (!final_step)
                global_barrier(&s_sense, tid, nblocks);
        }
    }
}

// ---------------------------------------------------------------------------
// Launch
// ---------------------------------------------------------------------------
extern "C" void kernel_launch(void* const* d_in, const int* in_sizes, int n_in,
                              void* d_out, int out_size) {
    const float* x  = (const float*)d_in[0];
    const int*   er = (const int*)d_in[1];
    const int*   ec = (const int*)d_in[2];
    const float* ev = (const float*)d_in[3];
    float* out = (float*)d_out;

    int ne = in_sizes[1];
    int nn = in_sizes[0] / DF;

    void *p_hy, *p_h0, *p_h1;
    cudaGetSymbolAddress(&p_hy, g_hy);
    cudaGetSymbolAddress(&p_h0, g_half0);
    cudaGetSymbolAddress(&p_h1, g_half1);

    // --- CSR build: exactly 5 launches before persistent_horner ---
    init_kernel<<<(nn + 256) / 256, 256>>>(nn);                       // [0]
    count_deg_kernel<<<(ne + 255) / 256, 256>>>(er, ev, ne);          // [1]

    int nscan = nn + 1;
    int nchunks = (nscan + 1023) / 1024;
    scan1_kernel<<<nchunks, 1024>>>(nscan);                           // [2]
    scan2_kernel<<<1, 32>>>(nchunks);                                 // [3]
    scan3_kernel<<<nchunks, 1024>>>(nscan);                           // [4]

    // --- Persistent expm-action kernel (scatter+seed in prologue) ---
    int dev = 0;
    cudaGetDevice(&dev);
    int nsm = 0;
    cudaDeviceGetAttribute(&nsm, cudaDevAttrMultiProcessorCount, dev);

    int nblocks = nsm;         // fallback
    size_t smem = 0;
    for (int nb = 8; nb >= 1; nb--) {
        int cand_blocks = nb * nsm;
        int R = (nn + cand_blocks - 1) / cand_blocks;
        size_t s = (size_t)R * 32 * sizeof(uint4);  // R * 512B
        cudaFuncSetAttribute(persistent_horner,
                             cudaFuncAttributeMaxDynamicSharedMemorySize,
                             (int)s);
        int got = 0;
        cudaOccupancyMaxActiveBlocksPerMultiprocessor(&got, persistent_horner,
                                                      256, s);
        if (got >= nb) {
            nblocks = cand_blocks;
            smem = s;
            break;
        }
    }
    int R = (nn + nblocks - 1) / nblocks;

    dim3 bd(32, 8);
    persistent_horner<<<nblocks, bd, smem>>>(                         // [5]
        (const float4*)x, er, ec, ev, (float4*)out,
        (uint4*)p_hy, (uint4*)p_h0, (uint4*)p_h1, nn, ne, R, nblocks);
    // Result is in `out`.
}

// round 15
// speedup vs baseline: 1.0514x; 1.0514x over previous
#include <cuda_runtime.h>
#include <cuda_fp16.h>

// Problem constants: 50000 nodes, 256 feats, 400000 edges,
// DIFF_T=1.0, N_SEG=4 (t_seg=0.25), N_TERMS=8.
#define NN_MAX 50000
#define DF 256
#define DF4 (DF / 4)
#define NE_MAX 400000

// Scratch (allocation-free: static device globals).
__device__ int   g_cnt[NN_MAX + 1];
__device__ int   g_rowptr[NN_MAX + 1];
__device__ int   g_fill[NN_MAX];
__device__ int   g_sums[64];
__device__ int   g_offs[64];
__device__ int2  g_cv[NE_MAX];           // packed {col, val-bits}
__device__ float g_deg[NN_MAX];
// fp16 state buffers: y mirror + z ping-pong.
__device__ __half g_hy[(size_t)NN_MAX * DF];
__device__ __half g_half0[(size_t)NN_MAX * DF];
__device__ __half g_half1[(size_t)NN_MAX * DF];

// Global software barrier state (replay-safe).
__device__ int g_bar_count;
__device__ int g_bar_sense;

// ---------------------------------------------------------------------------
// CSR build
// ---------------------------------------------------------------------------
__global__ void count_deg_kernel(const int* __restrict__ rows,
                                 const float* __restrict__ vals, int ne) {
    int e = blockIdx.x * blockDim.x + threadIdx.x;
    if (e < ne) {
        int r = rows[e];
        atomicAdd(&g_cnt[r], 1);
        atomicAdd(&g_deg[r], vals[e]);
    }
}

__global__ void scan1_kernel(int n) {
    __shared__ int sh[1024];
    int tid = threadIdx.x;
    int i = blockIdx.x * 1024 + tid;
    int v = (i < n) ? g_cnt[i] : 0;
    sh[tid] = v;
    __syncthreads();
    for (int off = 1; off < 1024; off <<= 1) {
        int t = (tid >= off) ? sh[tid - off] : 0;
        __syncthreads();
        sh[tid] += t;
        __syncthreads();
    }
    if (i < n) g_rowptr[i] = sh[tid] - v;
    if (tid == 1023) g_sums[blockIdx.x] = sh[1023];
}

__global__ void scan2_kernel(int nchunks) {
    if (blockIdx.x == 0 && threadIdx.x == 0) {
        int run = 0;
        for (int b = 0; b < nchunks; b++) {
            int s = g_sums[b];
            g_offs[b] = run;
            run += s;
        }
    }
}

__global__ void scan3_kernel(int n) {
    int i = blockIdx.x * 1024 + threadIdx.x;
    if (i < n) g_rowptr[i] += g_offs[blockIdx.x];
}

__global__ void scatter_kernel(const int* __restrict__ rows,
                               const int* __restrict__ cols,
                               const float* __restrict__ vals, int ne) {
    int e = blockIdx.x * blockDim.x + threadIdx.x;
    if (e < ne) {
        int r = rows[e];
        int pos = atomicAdd(&g_fill[r], 1);
        int2 cv;
        cv.x = cols[e];
        cv.y = __float_as_int(vals[e]);
        g_cv[pos] = cv;
    }
}

// Convert fp32 buffer -> fp16 mirror. Each thread: 8 floats -> one uint4.
__global__ void to_half_kernel(const float4* __restrict__ src,
                               uint4* __restrict__ dst, int n4) {
    int i = blockIdx.x * blockDim.x + threadIdx.x;
    if (i < n4) {
        float4 a = src[2 * i];
        float4 b = src[2 * i + 1];
        __half2 h[4];
        h[0] = __floats2half2_rn(a.x, a.y);
        h[1] = __floats2half2_rn(a.z, a.w);
        h[2] = __floats2half2_rn(b.x, b.y);
        h[3] = __floats2half2_rn(b.z, b.w);
        dst[i] = *(const uint4*)h;
    }
}

// ---------------------------------------------------------------------------
// One Horner row update (all-fp16 state), 8-edge unroll (MLP=8):
//   znew[r] = y[r] + coef * ( deg[r]*z[r] - sum_e val_e * z[col_e] )
//   hdst[r] = fp16(znew[r]);  if dst32: dst32[r] = znew[r]  (final step)
// One warp per row; thread f owns feats [8f, 8f+8).
// ---------------------------------------------------------------------------
__device__ __forceinline__ void horner_row(
    int r, int f,
    const uint4* __restrict__ hsrc,   // z mirror (gather + diag)
    const uint4* __restrict__ hy,     // y mirror (own-row read)
    uint4* __restrict__ hdst,
    float4* __restrict__ dst32,
    float coef)
{
    int start = g_rowptr[r];
    int end = g_rowptr[r + 1];

    float s0 = 0.f, s1 = 0.f, s2 = 0.f, s3 = 0.f;
    float s4 = 0.f, s5 = 0.f, s6 = 0.f, s7 = 0.f;

    for (int e = start; e < end; e += 8) {
        int last = end - 1;
        int2  cv[8];
        float w[8];
        uint4 u[8];
#pragma unroll
        for (int j = 0; j < 8; j++) {
            int ej = min(e + j, last);
            cv[j] = g_cv[ej];
            w[j] = (e + j < end) ? __int_as_float(cv[j].y) : 0.f;
        }
#pragma unroll
        for (int j = 0; j < 8; j++)
            u[j] = hsrc[(size_t)cv[j].x * 32 + f];   // 8 gathers in flight
#pragma unroll
        for (int j = 0; j < 8; j++) {
            const __half2* h = (const __half2*)&u[j];
            float wj = w[j];
            float2 p;
            p = __half22float2(h[0]); s0 = fmaf(wj, p.x, s0); s1 = fmaf(wj, p.y, s1);
            p = __half22float2(h[1]); s2 = fmaf(wj, p.x, s2); s3 = fmaf(wj, p.y, s3);
            p = __half22float2(h[2]); s4 = fmaf(wj, p.x, s4); s5 = fmaf(wj, p.y, s5);
            p = __half22float2(h[3]); s6 = fmaf(wj, p.x, s6); s7 = fmaf(wj, p.y, s7);
        }
    }

    // Diagonal term from the z mirror (own row, coalesced).
    float d = g_deg[r];
    uint4 um = hsrc[(size_t)r * 32 + f];
    const __half2* hm = (const __half2*)&um;
    float2 m01 = __half22float2(hm[0]);
    float2 m23 = __half22float2(hm[1]);
    float2 m45 = __half22float2(hm[2]);
    float2 m67 = __half22float2(hm[3]);

    // y term from the y mirror (own row, fp16).
    uint4 uy = hy[(size_t)r * 32 + f];
    const __half2* hyv = (const __half2*)&uy;
    float2 y01 = __half22float2(hyv[0]);
    float2 y23 = __half22float2(hyv[1]);
    float2 y45 = __half22float2(hyv[2]);
    float2 y67 = __half22float2(hyv[3]);

    float o0 = fmaf(coef, fmaf(d, m01.x, -s0), y01.x);
    float o1 = fmaf(coef, fmaf(d, m01.y, -s1), y01.y);
    float o2 = fmaf(coef, fmaf(d, m23.x, -s2), y23.x);
    float o3 = fmaf(coef, fmaf(d, m23.y, -s3), y23.y);
    float o4 = fmaf(coef, fmaf(d, m45.x, -s4), y45.x);
    float o5 = fmaf(coef, fmaf(d, m45.y, -s5), y45.y);
    float o6 = fmaf(coef, fmaf(d, m67.x, -s6), y67.x);
    float o7 = fmaf(coef, fmaf(d, m67.y, -s7), y67.y);

    if (dst32) {
        size_t base = (size_t)r * DF4 + 2 * f;
        dst32[base]     = make_float4(o0, o1, o2, o3);
        dst32[base + 1] = make_float4(o4, o5, o6, o7);
    }

    __half2 h[4];
    h[0] = __floats2half2_rn(o0, o1);
    h[1] = __floats2half2_rn(o2, o3);
    h[2] = __floats2half2_rn(o4, o5);
    h[3] = __floats2half2_rn(o6, o7);
    hdst[(size_t)r * 32 + f] = *(const uint4*)h;
}

// Smallest r in [0, nn] with (rowptr[r] + 4r) * GW >= target.
__device__ __forceinline__ int partition_point(long long target, int nn,
                                               long long GW) {
    int lo = 0, hi = nn;
    while (lo < hi) {
        int mid = (lo + hi) >> 1;
        long long key = ((long long)g_rowptr[mid] + 4LL * mid) * GW;
        if (key < target) lo = mid + 1; else hi = mid;
    }
    return lo;
}

// ---------------------------------------------------------------------------
// Persistent kernel: 4 segments x 8 Horner steps, global barrier between
// steps. Grid sized host-side via occupancy API (regs-aware), so the grid is
// exactly co-resident and the barrier cannot deadlock. blockDim = (32, 8).
// Contiguous edge-balanced row ranges per warp.
//   k=8: gather from hy (z=y);  k=7..2: ping-pong h0/h1;
//   k=1: write hy (next segment's y); final step also writes fp32 out.
// ---------------------------------------------------------------------------
__global__ void __launch_bounds__(256)
persistent_horner(float4* __restrict__ out,
                  uint4* __restrict__ hy,
                  uint4* __restrict__ h0,
                  uint4* __restrict__ h1,
                  int nn, int ne, int nblocks) {
    __shared__ int s_sense;
    int tid = threadIdx.y * 32 + threadIdx.x;
    if (tid == 0) s_sense = *(volatile int*)&g_bar_sense;
    __syncthreads();

    int gw = blockIdx.x * 8 + threadIdx.y;
    long long GW = (long long)nblocks * 8;
    int f = threadIdx.x;

    int r_lo, r_hi;
    if (f == 0) {
        long long C = (long long)ne + 4LL * nn;
        r_lo = partition_point((long long)gw * C, nn, GW);
        r_hi = partition_point((long long)(gw + 1) * C, nn, GW);
    }
    r_lo = __shfl_sync(0xFFFFFFFFu, r_lo, 0);
    r_hi = __shfl_sync(0xFFFFFFFFu, r_hi, 0);

    int p = 0;  // which of h0/h1 is next write target for k=8..2
    for (int seg = 0; seg < 4; seg++) {
        const uint4* cur = hy;  // z mirror starts as y
        for (int k = 8; k >= 1; k--) {
            float coef = -0.25f / (float)k;
            bool final_step = (seg == 3) && (k == 1);
            uint4* hd;
            if (k == 1) {
                hd = hy;  // becomes next segment's y
            } else {
                hd = p ? h1 : h0;
                p ^= 1;
            }
            float4* dst32 = final_step ? out : nullptr;

            for (int r = r_lo; r < r_hi; r++)
                horner_row(r, f, cur, hy, hd, dst32, coef);
            cur = hd;

            if (!final_step) {
                // Global sense-reversal barrier.
                __syncthreads();
                if (tid == 0) {
                    __threadfence();
                    int want = s_sense ^ 1;
                    int old = atomicAdd(&g_bar_count, 1);
                    if (old == nblocks - 1) {
                        g_bar_count = 0;
                        __threadfence();
                        *(volatile int*)&g_bar_sense = want;
                    } else {
                        while (*(volatile int*)&g_bar_sense != want)
                            __nanosleep(64);
                    }
                    __threadfence();
                    s_sense = want;
                }
                __syncthreads();
            }
        }
    }
}

// ---------------------------------------------------------------------------
// Launch
// ---------------------------------------------------------------------------
extern "C" void kernel_launch(void* const* d_in, const int* in_sizes, int n_in,
                              void* d_out, int out_size) {
    const float* x  = (const float*)d_in[0];
    const int*   er = (const int*)d_in[1];
    const int*   ec = (const int*)d_in[2];
    const float* ev = (const float*)d_in[3];
    float* out = (float*)d_out;

    int ne = in_sizes[1];
    int nn = in_sizes[0] / DF;

    void *p_cnt, *p_deg, *p_fill, *p_rowptr, *p_hy, *p_h0, *p_h1;
    cudaGetSymbolAddress(&p_cnt, g_cnt);
    cudaGetSymbolAddress(&p_deg, g_deg);
    cudaGetSymbolAddress(&p_fill, g_fill);
    cudaGetSymbolAddress(&p_rowptr, g_rowptr);
    cudaGetSymbolAddress(&p_hy, g_hy);
    cudaGetSymbolAddress(&p_h0, g_half0);
    cudaGetSymbolAddress(&p_h1, g_half1);

    // --- CSR build ---
    cudaMemsetAsync(p_cnt, 0, (size_t)(nn + 1) * sizeof(int));
    cudaMemsetAsync(p_deg, 0, (size_t)nn * sizeof(float));
    count_deg_kernel<<<(ne + 255) / 256, 256>>>(er, ev, ne);

    int nscan = nn + 1;
    int nchunks = (nscan + 1023) / 1024;
    scan1_kernel<<<nchunks, 1024>>>(nscan);
    scan2_kernel<<<1, 32>>>(nchunks);
    scan3_kernel<<<nchunks, 1024>>>(nscan);

    cudaMemcpyAsync(p_fill, p_rowptr, (size_t)nn * sizeof(int),
                    cudaMemcpyDeviceToDevice);
    scatter_kernel<<<(ne + 255) / 256, 256>>>(er, ec, ev, ne);

    // Seed fp16 y mirror with x.
    int n4 = nn * 32;  // uint4 count
    to_half_kernel<<<(n4 + 255) / 256, 256>>>((const float4*)x,
                                              (uint4*)p_hy, n4);

    // --- Persistent expm-action kernel (regs-aware co-resident grid) ---
    int dev = 0;
    cudaGetDevice(&dev);
    int nsm = 0;
    cudaDeviceGetAttribute(&nsm, cudaDevAttrMultiProcessorCount, dev);
    int nb_per_sm = 0;
    cudaOccupancyMaxActiveBlocksPerMultiprocessor(&nb_per_sm,
                                                  persistent_horner, 256, 0);
    if (nb_per_sm < 1) nb_per_sm = 1;
    int nblocks = nsm * nb_per_sm;

    dim3 bd(32, 8);
    persistent_horner<<<nblocks, bd>>>((float4*)out, (uint4*)p_hy,
                                       (uint4*)p_h0, (uint4*)p_h1,
                                       nn, ne, nblocks);
    // Result is in `out`.
}

// round 16
// speedup vs baseline: 1.0553x; 1.0038x over previous
#include <cuda_runtime.h>
#include <cuda_fp16.h>

// Problem constants: 50000 nodes, 256 feats, 400000 edges,
// DIFF_T=1.0, N_SEG=4 (t_seg=0.25), N_TERMS=8.
#define NN_MAX 50000
#define DF 256
#define DF4 (DF / 4)
#define NE_MAX 400000

// Scratch (allocation-free: static device globals).
__device__ int   g_cnt[NN_MAX + 1];
__device__ int   g_rowptr[NN_MAX + 1];
__device__ int   g_fill[NN_MAX];
__device__ int   g_sums[64];
__device__ int   g_offs[64];
__device__ int2  g_cv[NE_MAX];           // packed {col, val-bits}
__device__ float g_deg[NN_MAX];
// fp16 state buffers: y mirror + z ping-pong.
__device__ __half g_hy[(size_t)NN_MAX * DF];
__device__ __half g_half0[(size_t)NN_MAX * DF];
__device__ __half g_half1[(size_t)NN_MAX * DF];

// Global software barrier state (replay-safe).
__device__ int g_bar_count;
__device__ int g_bar_sense;

// ---------------------------------------------------------------------------
// CSR build
// ---------------------------------------------------------------------------
__global__ void count_deg_kernel(const int* __restrict__ rows,
                                 const float* __restrict__ vals, int ne) {
    int e = blockIdx.x * blockDim.x + threadIdx.x;
    if (e < ne) {
        int r = rows[e];
        atomicAdd(&g_cnt[r], 1);
        atomicAdd(&g_deg[r], vals[e]);
    }
}

__global__ void scan1_kernel(int n) {
    __shared__ int sh[1024];
    int tid = threadIdx.x;
    int i = blockIdx.x * 1024 + tid;
    int v = (i < n) ? g_cnt[i] : 0;
    sh[tid] = v;
    __syncthreads();
    for (int off = 1; off < 1024; off <<= 1) {
        int t = (tid >= off) ? sh[tid - off] : 0;
        __syncthreads();
        sh[tid] += t;
        __syncthreads();
    }
    if (i < n) g_rowptr[i] = sh[tid] - v;
    if (tid == 1023) g_sums[blockIdx.x] = sh[1023];
}

__global__ void scan2_kernel(int nchunks) {
    if (blockIdx.x == 0 && threadIdx.x == 0) {
        int run = 0;
        for (int b = 0; b < nchunks; b++) {
            int s = g_sums[b];
            g_offs[b] = run;
            run += s;
        }
    }
}

__global__ void scan3_kernel(int n) {
    int i = blockIdx.x * 1024 + threadIdx.x;
    if (i < n) g_rowptr[i] += g_offs[blockIdx.x];
}

__global__ void scatter_kernel(const int* __restrict__ rows,
                               const int* __restrict__ cols,
                               const float* __restrict__ vals, int ne) {
    int e = blockIdx.x * blockDim.x + threadIdx.x;
    if (e < ne) {
        int r = rows[e];
        int pos = atomicAdd(&g_fill[r], 1);
        int2 cv;
        cv.x = cols[e];
        cv.y = __float_as_int(vals[e]);
        g_cv[pos] = cv;
    }
}

// Convert fp32 buffer -> fp16 mirror. Each thread: 8 floats -> one uint4.
__global__ void to_half_kernel(const float4* __restrict__ src,
                               uint4* __restrict__ dst, int n4) {
    int i = blockIdx.x * blockDim.x + threadIdx.x;
    if (i < n4) {
        float4 a = src[2 * i];
        float4 b = src[2 * i + 1];
        __half2 h[4];
        h[0] = __floats2half2_rn(a.x, a.y);
        h[1] = __floats2half2_rn(a.z, a.w);
        h[2] = __floats2half2_rn(b.x, b.y);
        h[3] = __floats2half2_rn(b.z, b.w);
        dst[i] = *(const uint4*)h;
    }
}

// ---------------------------------------------------------------------------
// One Horner row update (all-fp16 state), 8-edge unroll (MLP=8):
//   znew[r] = y[r] + coef * ( deg[r]*z[r] - sum_e val_e * z[col_e] )
//   hdst[r] = fp16(znew[r]);  if dst32: dst32[r] = znew[r]  (final step)
// One warp per row; thread f owns feats [8f, 8f+8).
// ---------------------------------------------------------------------------
__device__ __forceinline__ void horner_row(
    int r, int f,
    const uint4* __restrict__ hsrc,   // z mirror (gather + diag)
    const uint4* __restrict__ hy,     // y mirror (own-row read)
    uint4* __restrict__ hdst,
    float4* __restrict__ dst32,
    float coef)
{
    int start = g_rowptr[r];
    int end = g_rowptr[r + 1];

    float s0 = 0.f, s1 = 0.f, s2 = 0.f, s3 = 0.f;
    float s4 = 0.f, s5 = 0.f, s6 = 0.f, s7 = 0.f;

    for (int e = start; e < end; e += 8) {
        int last = end - 1;
        int2  cv[8];
        float w[8];
        uint4 u[8];
#pragma unroll
        for (int j = 0; j < 8; j++) {
            int ej = min(e + j, last);
            cv[j] = g_cv[ej];
            w[j] = (e + j < end) ? __int_as_float(cv[j].y) : 0.f;
        }
#pragma unroll
        for (int j = 0; j < 8; j++)
            u[j] = hsrc[(size_t)cv[j].x * 32 + f];   // 8 gathers in flight
#pragma unroll
        for (int j = 0; j < 8; j++) {
            const __half2* h = (const __half2*)&u[j];
            float wj = w[j];
            float2 p;
            p = __half22float2(h[0]); s0 = fmaf(wj, p.x, s0); s1 = fmaf(wj, p.y, s1);
            p = __half22float2(h[1]); s2 = fmaf(wj, p.x, s2); s3 = fmaf(wj, p.y, s3);
            p = __half22float2(h[2]); s4 = fmaf(wj, p.x, s4); s5 = fmaf(wj, p.y, s5);
            p = __half22float2(h[3]); s6 = fmaf(wj, p.x, s6); s7 = fmaf(wj, p.y, s7);
        }
    }

    // Diagonal term from the z mirror (own row, coalesced).
    float d = g_deg[r];
    uint4 um = hsrc[(size_t)r * 32 + f];
    const __half2* hm = (const __half2*)&um;
    float2 m01 = __half22float2(hm[0]);
    float2 m23 = __half22float2(hm[1]);
    float2 m45 = __half22float2(hm[2]);
    float2 m67 = __half22float2(hm[3]);

    // y term from the y mirror (own row, fp16).
    uint4 uy = hy[(size_t)r * 32 + f];
    const __half2* hyv = (const __half2*)&uy;
    float2 y01 = __half22float2(hyv[0]);
    float2 y23 = __half22float2(hyv[1]);
    float2 y45 = __half22float2(hyv[2]);
    float2 y67 = __half22float2(hyv[3]);

    float o0 = fmaf(coef, fmaf(d, m01.x, -s0), y01.x);
    float o1 = fmaf(coef, fmaf(d, m01.y, -s1), y01.y);
    float o2 = fmaf(coef, fmaf(d, m23.x, -s2), y23.x);
    float o3 = fmaf(coef, fmaf(d, m23.y, -s3), y23.y);
    float o4 = fmaf(coef, fmaf(d, m45.x, -s4), y45.x);
    float o5 = fmaf(coef, fmaf(d, m45.y, -s5), y45.y);
    float o6 = fmaf(coef, fmaf(d, m67.x, -s6), y67.x);
    float o7 = fmaf(coef, fmaf(d, m67.y, -s7), y67.y);

    if (dst32) {
        size_t base = (size_t)r * DF4 + 2 * f;
        dst32[base]     = make_float4(o0, o1, o2, o3);
        dst32[base + 1] = make_float4(o4, o5, o6, o7);
    }

    __half2 h[4];
    h[0] = __floats2half2_rn(o0, o1);
    h[1] = __floats2half2_rn(o2, o3);
    h[2] = __floats2half2_rn(o4, o5);
    h[3] = __floats2half2_rn(o6, o7);
    hdst[(size_t)r * 32 + f] = *(const uint4*)h;
}

// Smallest r in [0, nn] with (rowptr[r] + 4r) * GW >= target.
__device__ __forceinline__ int partition_point(long long target, int nn,
                                               long long GW) {
    int lo = 0, hi = nn;
    while (lo < hi) {
        int mid = (lo + hi) >> 1;
        long long key = ((long long)g_rowptr[mid] + 4LL * mid) * GW;
        if (key < target) lo = mid + 1; else hi = mid;
    }
    return lo;
}

// ---------------------------------------------------------------------------
// Persistent kernel: 4 segments x 8 Horner steps, global barrier between
// steps. Grid sized host-side via occupancy API (regs-aware), so the grid is
// exactly co-resident and the barrier cannot deadlock. blockDim = (32, 8).
// Contiguous edge-balanced row ranges per warp.
//   k=8: gather from hy (z=y);  k=7..2: ping-pong h0/h1;
//   k=1: write hy (next segment's y); final step also writes fp32 out.
// ---------------------------------------------------------------------------
__global__ void __launch_bounds__(256)
persistent_horner(float4* __restrict__ out,
                  uint4* __restrict__ hy,
                  uint4* __restrict__ h0,
                  uint4* __restrict__ h1,
                  int nn, int ne, int nblocks) {
    __shared__ int s_sense;
    int tid = threadIdx.y * 32 + threadIdx.x;
    if (tid == 0) s_sense = *(volatile int*)&g_bar_sense;
    __syncthreads();

    int gw = blockIdx.x * 8 + threadIdx.y;
    long long GW = (long long)nblocks * 8;
    int f = threadIdx.x;

    int r_lo, r_hi;
    if (f == 0) {
        long long C = (long long)ne + 4LL * nn;
        r_lo = partition_point((long long)gw * C, nn, GW);
        r_hi = partition_point((long long)(gw + 1) * C, nn, GW);
    }
    r_lo = __shfl_sync(0xFFFFFFFFu, r_lo, 0);
    r_hi = __shfl_sync(0xFFFFFFFFu, r_hi, 0);

    int p = 0;  // which of h0/h1 is next write target for k=8..2
    for (int seg = 0; seg < 4; seg++) {
        const uint4* cur = hy;  // z mirror starts as y
        for (int k = 8; k >= 1; k--) {
            float coef = -0.25f / (float)k;
            bool final_step = (seg == 3) && (k == 1);
            uint4* hd;
            if (k == 1) {
                hd = hy;  // becomes next segment's y
            } else {
                hd = p ? h1 : h0;
                p ^= 1;
            }
            float4* dst32 = final_step ? out : nullptr;

            for (int r = r_lo; r < r_hi; r++)
                horner_row(r, f, cur, hy, hd, dst32, coef);
            cur = hd;

            if (!final_step) {
                // Global sense-reversal barrier.
                __syncthreads();
                if (tid == 0) {
                    __threadfence();
                    int want = s_sense ^ 1;
                    int old = atomicAdd(&g_bar_count, 1);
                    if (old == nblocks - 1) {
                        g_bar_count = 0;
                        __threadfence();
                        *(volatile int*)&g_bar_sense = want;
                    } else {
                        while (*(volatile int*)&g_bar_sense != want)
                            __nanosleep(64);
                    }
                    __threadfence();
                    s_sense = want;
                }
                __syncthreads();
            }
        }
    }
}

// ---------------------------------------------------------------------------
// Launch
// ---------------------------------------------------------------------------
extern "C" void kernel_launch(void* const* d_in, const int* in_sizes, int n_in,
                              void* d_out, int out_size) {
    const float* x  = (const float*)d_in[0];
    const int*   er = (const int*)d_in[1];
    const int*   ec = (const int*)d_in[2];
    const float* ev = (const float*)d_in[3];
    float* out = (float*)d_out;

    int ne = in_sizes[1];
    int nn = in_sizes[0] / DF;

    void *p_cnt, *p_deg, *p_fill, *p_rowptr, *p_hy, *p_h0, *p_h1;
    cudaGetSymbolAddress(&p_cnt, g_cnt);
    cudaGetSymbolAddress(&p_deg, g_deg);
    cudaGetSymbolAddress(&p_fill, g_fill);
    cudaGetSymbolAddress(&p_rowptr, g_rowptr);
    cudaGetSymbolAddress(&p_hy, g_hy);
    cudaGetSymbolAddress(&p_h0, g_half0);
    cudaGetSymbolAddress(&p_h1, g_half1);

    // --- CSR build ---
    cudaMemsetAsync(p_cnt, 0, (size_t)(nn + 1) * sizeof(int));
    cudaMemsetAsync(p_deg, 0, (size_t)nn * sizeof(float));
    count_deg_kernel<<<(ne + 255) / 256, 256>>>(er, ev, ne);

    int nscan = nn + 1;
    int nchunks = (nscan + 1023) / 1024;
    scan1_kernel<<<nchunks, 1024>>>(nscan);
    scan2_kernel<<<1, 32>>>(nchunks);
    scan3_kernel<<<nchunks, 1024>>>(nscan);

    cudaMemcpyAsync(p_fill, p_rowptr, (size_t)nn * sizeof(int),
                    cudaMemcpyDeviceToDevice);
    scatter_kernel<<<(ne + 255) / 256, 256>>>(er, ec, ev, ne);

    // Seed fp16 y mirror with x.
    int n4 = nn * 32;  // uint4 count
    to_half_kernel<<<(n4 + 255) / 256, 256>>>((const float4*)x,
                                              (uint4*)p_hy, n4);

    // --- Persistent expm-action kernel (regs-aware co-resident grid) ---
    int dev = 0;
    cudaGetDevice(&dev);
    int nsm = 0;
    cudaDeviceGetAttribute(&nsm, cudaDevAttrMultiProcessorCount, dev);
    int nb_per_sm = 0;
    cudaOccupancyMaxActiveBlocksPerMultiprocessor(&nb_per_sm,
                                                  persistent_horner, 256, 0);
    if (nb_per_sm < 1) nb_per_sm = 1;
    int nblocks = nsm * nb_per_sm;

    dim3 bd(32, 8);
    persistent_horner<<<nblocks, bd>>>((float4*)out, (uint4*)p_hy,
                                       (uint4*)p_h0, (uint4*)p_h1,
                                       nn, ne, nblocks);
    // Result is in `out`.
}

// round 17
// speedup vs baseline: 1.2357x; 1.1709x over previous
#include <cuda_runtime.h>
#include <cuda_fp16.h>

// Problem constants: 50000 nodes, 256 feats, 400000 edges,
// DIFF_T=1.0, N_SEG=4 (t_seg=0.25), N_TERMS=8.
#define NN_MAX 50000
#define DF 256
#define DF4 (DF / 4)
#define NE_MAX 400000

// Scratch (allocation-free: static device globals).
__device__ int   g_cnt[NN_MAX + 1];
__device__ int   g_rowptr[NN_MAX + 1];
__device__ int   g_fill[NN_MAX];
__device__ int   g_sums[64];
__device__ int   g_offs[64];
__device__ int2  g_cv[NE_MAX];           // packed {col, val-bits}
__device__ float g_deg[NN_MAX];
// fp16 state buffers: y mirror + z ping-pong.
__device__ __half g_hy[(size_t)NN_MAX * DF];
__device__ __half g_half0[(size_t)NN_MAX * DF];
__device__ __half g_half1[(size_t)NN_MAX * DF];

// Global software barrier state (replay-safe).
__device__ int g_bar_count;
__device__ int g_bar_sense;

// ---------------------------------------------------------------------------
// CSR build
// ---------------------------------------------------------------------------
__global__ void count_deg_kernel(const int* __restrict__ rows,
                                 const float* __restrict__ vals, int ne) {
    int e = blockIdx.x * blockDim.x + threadIdx.x;
    if (e < ne) {
        int r = rows[e];
        atomicAdd(&g_cnt[r], 1);
        atomicAdd(&g_deg[r], vals[e]);
    }
}

__global__ void scan1_kernel(int n) {
    __shared__ int sh[1024];
    int tid = threadIdx.x;
    int i = blockIdx.x * 1024 + tid;
    int v = (i < n) ? g_cnt[i] : 0;
    sh[tid] = v;
    __syncthreads();
    for (int off = 1; off < 1024; off <<= 1) {
        int t = (tid >= off) ? sh[tid - off] : 0;
        __syncthreads();
        sh[tid] += t;
        __syncthreads();
    }
    if (i < n) g_rowptr[i] = sh[tid] - v;
    if (tid == 1023) g_sums[blockIdx.x] = sh[1023];
}

__global__ void scan2_kernel(int nchunks) {
    if (blockIdx.x == 0 && threadIdx.x == 0) {
        int run = 0;
        for (int b = 0; b < nchunks; b++) {
            int s = g_sums[b];
            g_offs[b] = run;
            run += s;
        }
    }
}

__global__ void scan3_kernel(int n) {
    int i = blockIdx.x * 1024 + threadIdx.x;
    if (i < n) g_rowptr[i] += g_offs[blockIdx.x];
}

__global__ void scatter_kernel(const int* __restrict__ rows,
                               const int* __restrict__ cols,
                               const float* __restrict__ vals, int ne) {
    int e = blockIdx.x * blockDim.x + threadIdx.x;
    if (e < ne) {
        int r = rows[e];
        int pos = atomicAdd(&g_fill[r], 1);
        int2 cv;
        cv.x = cols[e];
        cv.y = __float_as_int(vals[e]);
        g_cv[pos] = cv;
    }
}

// Convert fp32 buffer -> fp16 mirror. Each thread: 8 floats -> one uint4.
__global__ void to_half_kernel(const float4* __restrict__ src,
                               uint4* __restrict__ dst, int n4) {
    int i = blockIdx.x * blockDim.x + threadIdx.x;
    if (i < n4) {
        float4 a = src[2 * i];
        float4 b = src[2 * i + 1];
        __half2 h[4];
        h[0] = __floats2half2_rn(a.x, a.y);
        h[1] = __floats2half2_rn(a.z, a.w);
        h[2] = __floats2half2_rn(b.x, b.y);
        h[3] = __floats2half2_rn(b.z, b.w);
        dst[i] = *(const uint4*)h;
    }
}

// ---------------------------------------------------------------------------
// One Horner row update (all-fp16 state), 4-edge unroll (MLP=4):
//   znew[r] = y[r] + coef * ( deg[r]*z[r] - sum_e val_e * z[col_e] )
//   hdst[r] = fp16(znew[r]);  if dst32: dst32[r] = znew[r]  (final step)
// One warp per row; thread f owns feats [8f, 8f+8).
// ---------------------------------------------------------------------------
__device__ __forceinline__ void horner_row(
    int r, int f,
    const uint4* __restrict__ hsrc,   // z mirror (gather + diag)
    const uint4* __restrict__ hy,     // y mirror (own-row read)
    uint4* __restrict__ hdst,
    float4* __restrict__ dst32,
    float coef)
{
    int start = g_rowptr[r];
    int end = g_rowptr[r + 1];

    float s0 = 0.f, s1 = 0.f, s2 = 0.f, s3 = 0.f;
    float s4 = 0.f, s5 = 0.f, s6 = 0.f, s7 = 0.f;

    for (int e = start; e < end; e += 4) {
        int last = end - 1;
        int e1 = min(e + 1, last);
        int e2 = min(e + 2, last);
        int e3 = min(e + 3, last);
        int2 cv0 = g_cv[e];
        int2 cv1 = g_cv[e1];
        int2 cv2 = g_cv[e2];
        int2 cv3 = g_cv[e3];
        float w0 = __int_as_float(cv0.y);
        float w1 = (e + 1 < end) ? __int_as_float(cv1.y) : 0.f;
        float w2 = (e + 2 < end) ? __int_as_float(cv2.y) : 0.f;
        float w3 = (e + 3 < end) ? __int_as_float(cv3.y) : 0.f;
        uint4 u0 = hsrc[(size_t)cv0.x * 32 + f];
        uint4 u1 = hsrc[(size_t)cv1.x * 32 + f];
        uint4 u2 = hsrc[(size_t)cv2.x * 32 + f];
        uint4 u3 = hsrc[(size_t)cv3.x * 32 + f];

        const __half2* h0 = (const __half2*)&u0;
        const __half2* h1 = (const __half2*)&u1;
        const __half2* h2 = (const __half2*)&u2;
        const __half2* h3 = (const __half2*)&u3;
        float2 p;
        p = __half22float2(h0[0]); s0 = fmaf(w0, p.x, s0); s1 = fmaf(w0, p.y, s1);
        p = __half22float2(h0[1]); s2 = fmaf(w0, p.x, s2); s3 = fmaf(w0, p.y, s3);
        p = __half22float2(h0[2]); s4 = fmaf(w0, p.x, s4); s5 = fmaf(w0, p.y, s5);
        p = __half22float2(h0[3]); s6 = fmaf(w0, p.x, s6); s7 = fmaf(w0, p.y, s7);
        p = __half22float2(h1[0]); s0 = fmaf(w1, p.x, s0); s1 = fmaf(w1, p.y, s1);
        p = __half22float2(h1[1]); s2 = fmaf(w1, p.x, s2); s3 = fmaf(w1, p.y, s3);
        p = __half22float2(h1[2]); s4 = fmaf(w1, p.x, s4); s5 = fmaf(w1, p.y, s5);
        p = __half22float2(h1[3]); s6 = fmaf(w1, p.x, s6); s7 = fmaf(w1, p.y, s7);
        p = __half22float2(h2[0]); s0 = fmaf(w2, p.x, s0); s1 = fmaf(w2, p.y, s1);
        p = __half22float2(h2[1]); s2 = fmaf(w2, p.x, s2); s3 = fmaf(w2, p.y, s3);
        p = __half22float2(h2[2]); s4 = fmaf(w2, p.x, s4); s5 = fmaf(w2, p.y, s5);
        p = __half22float2(h2[3]); s6 = fmaf(w2, p.x, s6); s7 = fmaf(w2, p.y, s7);
        p = __half22float2(h3[0]); s0 = fmaf(w3, p.x, s0); s1 = fmaf(w3, p.y, s1);
        p = __half22float2(h3[1]); s2 = fmaf(w3, p.x, s2); s3 = fmaf(w3, p.y, s3);
        p = __half22float2(h3[2]); s4 = fmaf(w3, p.x, s4); s5 = fmaf(w3, p.y, s5);
        p = __half22float2(h3[3]); s6 = fmaf(w3, p.x, s6); s7 = fmaf(w3, p.y, s7);
    }

    // Diagonal term from the z mirror (own row, coalesced).
    float d = g_deg[r];
    uint4 um = hsrc[(size_t)r * 32 + f];
    const __half2* hm = (const __half2*)&um;
    float2 m01 = __half22float2(hm[0]);
    float2 m23 = __half22float2(hm[1]);
    float2 m45 = __half22float2(hm[2]);
    float2 m67 = __half22float2(hm[3]);

    // y term from the y mirror (own row, fp16).
    uint4 uy = hy[(size_t)r * 32 + f];
    const __half2* hyv = (const __half2*)&uy;
    float2 y01 = __half22float2(hyv[0]);
    float2 y23 = __half22float2(hyv[1]);
    float2 y45 = __half22float2(hyv[2]);
    float2 y67 = __half22float2(hyv[3]);

    float o0 = fmaf(coef, fmaf(d, m01.x, -s0), y01.x);
    float o1 = fmaf(coef, fmaf(d, m01.y, -s1), y01.y);
    float o2 = fmaf(coef, fmaf(d, m23.x, -s2), y23.x);
    float o3 = fmaf(coef, fmaf(d, m23.y, -s3), y23.y);
    float o4 = fmaf(coef, fmaf(d, m45.x, -s4), y45.x);
    float o5 = fmaf(coef, fmaf(d, m45.y, -s5), y45.y);
    float o6 = fmaf(coef, fmaf(d, m67.x, -s6), y67.x);
    float o7 = fmaf(coef, fmaf(d, m67.y, -s7), y67.y);

    if (dst32) {
        size_t base = (size_t)r * DF4 + 2 * f;
        dst32[base]     = make_float4(o0, o1, o2, o3);
        dst32[base + 1] = make_float4(o4, o5, o6, o7);
    }

    __half2 h[4];
    h[0] = __floats2half2_rn(o0, o1);
    h[1] = __floats2half2_rn(o2, o3);
    h[2] = __floats2half2_rn(o4, o5);
    h[3] = __floats2half2_rn(o6, o7);
    hdst[(size_t)r * 32 + f] = *(const uint4*)h;
}

// Smallest r in [0, nn] with (rowptr[r] + 4r) * GW >= target.
__device__ __forceinline__ int partition_point(long long target, int nn,
                                               long long GW) {
    int lo = 0, hi = nn;
    while (lo < hi) {
        int mid = (lo + hi) >> 1;
        long long key = ((long long)g_rowptr[mid] + 4LL * mid) * GW;
        if (key < target) lo = mid + 1; else hi = mid;
    }
    return lo;
}

// ---------------------------------------------------------------------------
// Persistent kernel: 4 segments x 8 Horner steps, global barrier between
// steps. __launch_bounds__(256, 4) pins regs <= 64 so 4 blocks/SM are
// co-resident (32 warps/SM of gather coverage); the occupancy API sizes the
// grid to exactly that, keeping the barrier deadlock-free. blockDim = (32,8).
// Contiguous edge-balanced row ranges per warp.
//   k=8: gather from hy (z=y);  k=7..2: ping-pong h0/h1;
//   k=1: write hy (next segment's y); final step also writes fp32 out.
// ---------------------------------------------------------------------------
__global__ void __launch_bounds__(256, 4)
persistent_horner(float4* __restrict__ out,
                  uint4* __restrict__ hy,
                  uint4* __restrict__ h0,
                  uint4* __restrict__ h1,
                  int nn, int ne, int nblocks) {
    __shared__ int s_sense;
    int tid = threadIdx.y * 32 + threadIdx.x;
    if (tid == 0) s_sense = *(volatile int*)&g_bar_sense;
    __syncthreads();

    int gw = blockIdx.x * 8 + threadIdx.y;
    long long GW = (long long)nblocks * 8;
    int f = threadIdx.x;

    int r_lo, r_hi;
    if (f == 0) {
        long long C = (long long)ne + 4LL * nn;
        r_lo = partition_point((long long)gw * C, nn, GW);
        r_hi = partition_point((long long)(gw + 1) * C, nn, GW);
    }
    r_lo = __shfl_sync(0xFFFFFFFFu, r_lo, 0);
    r_hi = __shfl_sync(0xFFFFFFFFu, r_hi, 0);

    int p = 0;  // which of h0/h1 is next write target for k=8..2
    for (int seg = 0; seg < 4; seg++) {
        const uint4* cur = hy;  // z mirror starts as y
        for (int k = 8; k >= 1; k--) {
            float coef = -0.25f / (float)k;
            bool final_step = (seg == 3) && (k == 1);
            uint4* hd;
            if (k == 1) {
                hd = hy;  // becomes next segment's y
            } else {
                hd = p ? h1 : h0;
                p ^= 1;
            }
            float4* dst32 = final_step ? out : nullptr;

            for (int r = r_lo; r < r_hi; r++)
                horner_row(r, f, cur, hy, hd, dst32, coef);
            cur = hd;

            if (!final_step) {
                // Global sense-reversal barrier.
                __syncthreads();
                if (tid == 0) {
                    __threadfence();
                    int want = s_sense ^ 1;
                    int old = atomicAdd(&g_bar_count, 1);
                    if (old == nblocks - 1) {
                        g_bar_count = 0;
                        __threadfence();
                        *(volatile int*)&g_bar_sense = want;
                    } else {
                        while (*(volatile int*)&g_bar_sense != want)
                            __nanosleep(64);
                    }
                    __threadfence();
                    s_sense = want;
                }
                __syncthreads();
            }
        }
    }
}

// ---------------------------------------------------------------------------
// Launch
// ---------------------------------------------------------------------------
extern "C" void kernel_launch(void* const* d_in, const int* in_sizes, int n_in,
                              void* d_out, int out_size) {
    const float* x  = (const float*)d_in[0];
    const int*   er = (const int*)d_in[1];
    const int*   ec = (const int*)d_in[2];
    const float* ev = (const float*)d_in[3];
    float* out = (float*)d_out;

    int ne = in_sizes[1];
    int nn = in_sizes[0] / DF;

    void *p_cnt, *p_deg, *p_fill, *p_rowptr, *p_hy, *p_h0, *p_h1;
    cudaGetSymbolAddress(&p_cnt, g_cnt);
    cudaGetSymbolAddress(&p_deg, g_deg);
    cudaGetSymbolAddress(&p_fill, g_fill);
    cudaGetSymbolAddress(&p_rowptr, g_rowptr);
    cudaGetSymbolAddress(&p_hy, g_hy);
    cudaGetSymbolAddress(&p_h0, g_half0);
    cudaGetSymbolAddress(&p_h1, g_half1);

    // --- CSR build ---
    cudaMemsetAsync(p_cnt, 0, (size_t)(nn + 1) * sizeof(int));
    cudaMemsetAsync(p_deg, 0, (size_t)nn * sizeof(float));
    count_deg_kernel<<<(ne + 255) / 256, 256>>>(er, ev, ne);

    int nscan = nn + 1;
    int nchunks = (nscan + 1023) / 1024;
    scan1_kernel<<<nchunks, 1024>>>(nscan);
    scan2_kernel<<<1, 32>>>(nchunks);
    scan3_kernel<<<nchunks, 1024>>>(nscan);

    cudaMemcpyAsync(p_fill, p_rowptr, (size_t)nn * sizeof(int),
                    cudaMemcpyDeviceToDevice);
    scatter_kernel<<<(ne + 255) / 256, 256>>>(er, ec, ev, ne);

    // Seed fp16 y mirror with x.
    int n4 = nn * 32;  // uint4 count
    to_half_kernel<<<(n4 + 255) / 256, 256>>>((const float4*)x,
                                              (uint4*)p_hy, n4);

    // --- Persistent expm-action kernel (regs-aware co-resident grid) ---
    int dev = 0;
    cudaGetDevice(&dev);
    int nsm = 0;
    cudaDeviceGetAttribute(&nsm, cudaDevAttrMultiProcessorCount, dev);
    int nb_per_sm = 0;
    cudaOccupancyMaxActiveBlocksPerMultiprocessor(&nb_per_sm,
                                                  persistent_horner, 256, 0);
    if (nb_per_sm < 1) nb_per_sm = 1;
    int nblocks = nsm * nb_per_sm;

    dim3 bd(32, 8);
    persistent_horner<<<nblocks, bd>>>((float4*)out, (uint4*)p_hy,
                                       (uint4*)p_h0, (uint4*)p_h1,
                                       nn, ne, nblocks);
    // Result is in `out`.
}